// round 16
// baseline (speedup 1.0000x reference)
#include <cuda_runtime.h>
#include <math.h>

#define Bc   8
#define Cc   48
#define Nn   4096
#define KK   9
#define NBc  32768          // B*N
#define Ec   (Bc*Nn*KK)     // 294912

// -------- scratch (static device globals; no allocation) --------
__device__ float g_xnT[Bc*Cc*Nn];   // normalized features, CHANNEL-major [b][c][n]
__device__ float g_nodes[NBc*Cc];   // raw features, node-major
__device__ float g_sq[NBc];         // sum of squares of normalized row
__device__ int   g_nn[NBc*KK];      // knn indices (within batch, 0..N-1)
__device__ int   g_deg[NBc];
__device__ float g_dinv[NBc];
__device__ float g_tx1[NBc*Cc];

// faithful replication of jnp.linspace(0, 8, E).astype(int32):
// value_i = fl(fl(i) * fl(8/294911)), truncated toward zero.
__device__ __forceinline__ int edge_count(int i) {
    const float STEP = 8.0f / 294911.0f;
    return (int)((float)i * STEP);
}

// monotone float->uint map: preserves < ordering for all finite floats
__device__ __forceinline__ unsigned int fmono(float d) {
    unsigned int u = __float_as_uint(d);
    return (u & 0x80000000u) ? ~u : (u | 0x80000000u);
}

// packed f32x2 helpers (element-wise IEEE fp32: bit-identical to 2x fmaf)
__device__ __forceinline__ unsigned long long pack_dup(float v) {
    unsigned long long r;
    asm("mov.b64 %0, {%1, %1};" : "=l"(r) : "r"(__float_as_uint(v)));
    return r;
}
__device__ __forceinline__ void fma2(unsigned long long& acc,
                                     unsigned long long a, unsigned long long b) {
    asm("fma.rn.f32x2 %0, %1, %2, %0;" : "+l"(acc) : "l"(a), "l"(b));
}
__device__ __forceinline__ void unpack2(unsigned long long p, float& lo, float& hi) {
    unsigned int l, h;
    asm("mov.b64 {%0, %1}, %2;" : "=r"(l), "=r"(h) : "l"(p));
    lo = __uint_as_float(l); hi = __uint_as_float(h);
}

// ---------------- prep: normalize; emit channel-major + node-major ----------------
__global__ void prep_kernel(const float* __restrict__ x) {
    int node = blockIdx.x * blockDim.x + threadIdx.x;
    if (node >= NBc) return;
    int b = node >> 12, n = node & (Nn - 1);
    const float* xb = x + (size_t)b * Cc * Nn + n;
    float v[Cc];
    float ss = 0.f;
#pragma unroll
    for (int c = 0; c < Cc; c++) { v[c] = xb[c * Nn]; ss += v[c] * v[c]; }
    float m = fmaxf(sqrtf(ss), 1e-12f);
    float sq = 0.f;
    float* xT = g_xnT + (size_t)b * Cc * Nn + n;
#pragma unroll
    for (int c = 0; c < Cc; c++) {
        float xv = v[c] / m;
        xT[c * Nn]             = xv;   // channel-major (coalesced across threads)
        g_nodes[node * Cc + c] = v[c];
        sq += xv * xv;
    }
    g_sq[node]  = sq;
    g_deg[node] = 0;
}

// ---------------- KNN: tiled distances + fused top-9 ----------------
// 128 threads/CTA at OCCUPANCY 4 (16 warps/SM). Each thread COMPUTES
// 8 rows x 8 cols with XOR-relabeled accumulators (acc[rr] = row r0+(rr^cs));
// after each tile an oct-transpose via shfl_xor hands every thread ALL 64
// cols of its one owned row (r0+cs). One reg-resident top-9 list per thread.
#define QT 128
#define MT 64
#define TH 128

__global__ __launch_bounds__(TH, 4) void knn_kernel() {
    __shared__ float qs[Cc * QT];        // [k*128 + r]                (24 KB)
    __shared__ float ms[2][Cc * MT];     // [k*64 + perm(c)] ping-pong (24 KB)
    __shared__ float sqm[2][MT];

    int t    = threadIdx.x;
    int r0   = (t >> 3) * 8;      // oct base row: 0,8,...,120
    int cs   = t & 7;             // column segment 0..7 (8 cols each)
    int cseg = cs * 8;
    int b    = blockIdx.y;
    int qBase = blockIdx.x * QT;
    int nodeBase = b * Nn;
    const float* xT = g_xnT + (size_t)b * Cc * Nn;

    // qs: straight coalesced copy (already k-major). Cc*QT/4 = 1536 float4s.
    for (int i = t; i < Cc * 32; i += TH) {
        int k = i >> 5, c4 = i & 31;
        *(float4*)&qs[k * QT + c4 * 4] =
            *(const float4*)&xT[k * Nn + qBase + c4 * 4];
    }
    // preload tile 0: col-chunk c4 -> float offset (c4&1)*32 + (c4>>1)*4
    for (int i = t; i < Cc * 16; i += TH) {
        int k = i >> 4, c4 = i & 15;
        int dp = ((c4 & 1) << 5) + ((c4 >> 1) << 2);
        *(float4*)&ms[0][k * MT + dp] =
            *(const float4*)&xT[k * Nn + c4 * 4];
    }
    if (t < MT) sqm[0][t] = g_sq[nodeBase + t];
    float sqq = g_sq[nodeBase + qBase + r0 + cs];   // the ONE owned row

    // reg-resident top-9 list for the owned row
    unsigned long long lst[KK];
#pragma unroll
    for (int s = 0; s < KK; s++) lst[s] = 0xFF800000FFFFFFFFULL;
    unsigned int thr = 0xFF800000u;

    __syncthreads();

    int p = 0;
    for (int mb = 0; mb < Nn; mb += MT) {
        if (mb + MT < Nn) {
            for (int i = t; i < Cc * 16; i += TH) {
                int k = i >> 4, c4 = i & 15;
                int dp = ((c4 & 1) << 5) + ((c4 >> 1) << 2);
                *(float4*)&ms[1 - p][k * MT + dp] =
                    *(const float4*)&xT[k * Nn + (mb + MT) + c4 * 4];
            }
            if (t < MT) sqm[1 - p][t] = g_sq[nodeBase + mb + MT + t];
        }

        const float* msp = ms[p];
        unsigned long long acc[8][4];   // [relabeled row][col-pair]
#pragma unroll
        for (int r = 0; r < 8; r++)
#pragma unroll
            for (int j = 0; j < 4; j++) acc[r][j] = 0ULL;

        // q base for this thread's oct, with XOR relabeling folded in:
        // acc[rr] accumulates row r0 + (rr ^ cs)
        const float* qb = &qs[r0];
#pragma unroll 4
        for (int k = 0; k < Cc; k++) {
            const float* qk = qb + k * QT;
            const unsigned long long* mk =
                (const unsigned long long*)&msp[k * MT];
            unsigned long long m0 = mk[cs * 2],      m1 = mk[cs * 2 + 1];
            unsigned long long m2 = mk[16 + cs * 2], m3 = mk[16 + cs * 2 + 1];
#pragma unroll
            for (int rr = 0; rr < 8; rr++) {
                unsigned long long qq = pack_dup(qk[rr ^ cs]);
                fma2(acc[rr][0], qq, m0);
                fma2(acc[rr][1], qq, m1);
                fma2(acc[rr][2], qq, m2);
                fma2(acc[rr][3], qq, m3);
            }
        }

        // selection: d=0 is own segment; rounds d=1..7 receive partner t^d's
        // acc[d] = my row (r0+cs), their column segment (cs^d)*8.
#pragma unroll
        for (int d = 0; d < 8; d++) {
            unsigned long long v[4];
            if (d == 0) {
#pragma unroll
                for (int j = 0; j < 4; j++) v[j] = acc[0][j];
            } else {
#pragma unroll
                for (int j = 0; j < 4; j++)
                    v[j] = __shfl_xor_sync(0xffffffffu, acc[d][j], d);
            }
            int colbase = cseg ^ (d * 8);    // (cs^d)*8
#pragma unroll
            for (int jp = 0; jp < 4; jp++) {
                float v0, v1;
                unpack2(v[jp], v0, v1);
#pragma unroll
                for (int e = 0; e < 2; e++) {
                    int   col = colbase + 2 * jp + e;
                    float dot = e ? v1 : v0;
                    float dd  = (sqq + sqm[p][col]) - 2.f * dot;
                    unsigned int dm = fmono(dd);
                    if (dm <= thr) {
                        unsigned long long key =
                            ((unsigned long long)dm << 32) |
                            (unsigned int)(mb + col);
                        if (key < lst[KK - 1]) {
                            lst[KK - 1] = key;
#pragma unroll
                            for (int s = KK - 1; s > 0; --s) {
                                if (lst[s] < lst[s - 1]) {
                                    unsigned long long tmp = lst[s];
                                    lst[s] = lst[s - 1]; lst[s - 1] = tmp;
                                }
                            }
                            thr = (unsigned int)(lst[KK - 1] >> 32);
                        }
                    }
                }
            }
        }

        __syncthreads();
        p ^= 1;
    }

    // exclusive row ownership: write out directly, no merge
    {
        int nrow = nodeBase + qBase + r0 + cs;
#pragma unroll
        for (int s = 0; s < KK; s++)
            g_nn[nrow * KK + s] = (int)(unsigned int)(lst[s] & 0xFFFFFFFFu);
    }
}

// ---------------- degree (int atomics: deterministic) ----------------
__global__ void deg_kernel() {
    int i = blockIdx.x * blockDim.x + threadIdx.x;
    if (i >= Ec) return;
    int cnt  = edge_count(i);
    int rown = i / KK;              // b*N + n
    int n    = rown & (Nn - 1);
    int m    = g_nn[i];
    int src  = m + cnt * Nn;
    int dst  = n + cnt * Nn;
    if (src < NBc && dst < NBc) atomicAdd(&g_deg[src], 1);
}

__global__ void dinv_kernel() {
    int i = blockIdx.x * blockDim.x + threadIdx.x;
    if (i >= NBc) return;
    int d = g_deg[i];
    g_dinv[i] = (d > 0) ? (1.0f / sqrtf((float)d)) : 0.0f;
}

// ---------------- Tx1: deterministic gather-side aggregation ----------------
__global__ void tx1_kernel() {
    int flat = blockIdx.x * blockDim.x + threadIdx.x;
    if (flat >= NBc * Cc) return;
    int d  = flat / Cc, ch = flat % Cc;
    int q  = d >> 12, n = d & (Nn - 1);
    float dv = g_dinv[d];
    float acc = 0.f;
#pragma unroll
    for (int bb = 0; bb < 2; bb++) {
        int bp = q - 1 + bb;
        if (bp < 0 || bp >= Bc) continue;
        int ibase = (bp * Nn + n) * KK;
#pragma unroll
        for (int j = 0; j < KK; j++) {
            int i = ibase + j;
            if (edge_count(i) == q) {
                int src = g_nn[i] + q * Nn;   // always < NB since q <= 7
                acc = fmaf(-dv * g_dinv[src], g_nodes[src * Cc + ch], acc);
            }
        }
    }
    g_tx1[flat] = acc;
}

// ---------------- epilogue: out = nodes@W0 + Tx1@W1 + bias ----------------
__global__ void out_kernel(const float* __restrict__ W0, const float* __restrict__ W1,
                           const float* __restrict__ bias, float* __restrict__ out) {
    __shared__ float sW0[Cc * Cc], sW1[Cc * Cc], sb[Cc];
    int t = threadIdx.x;
    for (int i = t; i < Cc * Cc; i += blockDim.x) { sW0[i] = W0[i]; sW1[i] = W1[i]; }
    if (t < Cc) sb[t] = bias[t];
    __syncthreads();
    int flat = blockIdx.x * blockDim.x + t;
    if (flat >= NBc * Cc) return;
    int d = flat / Cc, co = flat % Cc;
    const float* nrow = &g_nodes[d * Cc];
    const float* trow = &g_tx1[d * Cc];
    float acc = sb[co];
#pragma unroll
    for (int k = 0; k < Cc; k++)
        acc = fmaf(nrow[k], sW0[k * Cc + co], fmaf(trow[k], sW1[k * Cc + co], acc));
    out[flat] = acc;
}

// ---------------- launch ----------------
extern "C" void kernel_launch(void* const* d_in, const int* in_sizes, int n_in,
                              void* d_out, int out_size) {
    const float* x    = (const float*)d_in[0];
    const float* W0   = (const float*)d_in[1];
    const float* W1   = (const float*)d_in[2];
    const float* bias = (const float*)d_in[3];
    float* out = (float*)d_out;
    (void)in_sizes; (void)n_in; (void)out_size;

    prep_kernel<<<NBc / 256, 256>>>(x);
    dim3 gknn(Nn / QT, Bc);
    knn_kernel<<<gknn, TH>>>();
    deg_kernel<<<(Ec + 255) / 256, 256>>>();
    dinv_kernel<<<NBc / 256, 256>>>();
    tx1_kernel<<<(NBc * Cc) / 256, 256>>>();
    out_kernel<<<(NBc * Cc) / 256, 256>>>(W0, W1, bias, out);
}

// round 17
// speedup vs baseline: 1.3218x; 1.3218x over previous
#include <cuda_runtime.h>
#include <math.h>

#define Bc   8
#define Cc   48
#define Nn   4096
#define KK   9
#define NBc  32768          // B*N
#define Ec   (Bc*Nn*KK)     // 294912

// -------- scratch (static device globals; no allocation) --------
__device__ float g_xnT[Bc*Cc*Nn];   // normalized features, CHANNEL-major [b][c][n]
__device__ float g_nodes[NBc*Cc];   // raw features, node-major
__device__ float g_sq[NBc];         // sum of squares of normalized row
__device__ int   g_nn[NBc*KK];      // knn indices (within batch, 0..N-1)
__device__ int   g_deg[NBc];
__device__ float g_dinv[NBc];
__device__ float g_tx1[NBc*Cc];

// faithful replication of jnp.linspace(0, 8, E).astype(int32):
// value_i = fl(fl(i) * fl(8/294911)), truncated toward zero.
__device__ __forceinline__ int edge_count(int i) {
    const float STEP = 8.0f / 294911.0f;
    return (int)((float)i * STEP);
}

// monotone float->uint map: preserves < ordering for all finite floats
__device__ __forceinline__ unsigned int fmono(float d) {
    unsigned int u = __float_as_uint(d);
    return (u & 0x80000000u) ? ~u : (u | 0x80000000u);
}

// packed f32x2 helpers (element-wise IEEE fp32: bit-identical to 2x fmaf)
__device__ __forceinline__ unsigned long long pack_dup(float v) {
    unsigned long long r;
    asm("mov.b64 %0, {%1, %1};" : "=l"(r) : "r"(__float_as_uint(v)));
    return r;
}
__device__ __forceinline__ void fma2(unsigned long long& acc,
                                     unsigned long long a, unsigned long long b) {
    asm("fma.rn.f32x2 %0, %1, %2, %0;" : "+l"(acc) : "l"(a), "l"(b));
}
__device__ __forceinline__ void unpack2(unsigned long long p, float& lo, float& hi) {
    unsigned int l, h;
    asm("mov.b64 {%0, %1}, %2;" : "=r"(l), "=r"(h) : "l"(p));
    lo = __uint_as_float(l); hi = __uint_as_float(h);
}

// ---------------- prep: normalize; emit channel-major + node-major ----------------
__global__ void prep_kernel(const float* __restrict__ x) {
    int node = blockIdx.x * blockDim.x + threadIdx.x;
    if (node >= NBc) return;
    int b = node >> 12, n = node & (Nn - 1);
    const float* xb = x + (size_t)b * Cc * Nn + n;
    float v[Cc];
    float ss = 0.f;
#pragma unroll
    for (int c = 0; c < Cc; c++) { v[c] = xb[c * Nn]; ss += v[c] * v[c]; }
    float m = fmaxf(sqrtf(ss), 1e-12f);
    float sq = 0.f;
    float* xT = g_xnT + (size_t)b * Cc * Nn + n;
#pragma unroll
    for (int c = 0; c < Cc; c++) {
        float xv = v[c] / m;
        xT[c * Nn]             = xv;   // channel-major (coalesced across threads)
        g_nodes[node * Cc + c] = v[c];
        sq += xv * xv;
    }
    g_sq[node]  = sq;
    g_deg[node] = 0;
}

// ---------------- KNN (round-12 winner, verbatim) ----------------
// Block 256, QT=128, MT=64. Each thread COMPUTES 4 query rows x 8 cols
// but SELECTS for only 2 rows; sibling t^4 exchange hands over the other
// two rows' dot products, so reg lists stay at 2x9 u64 (no spills, occ 2).
#define QT 128
#define MT 64

__global__ __launch_bounds__(256, 2) void knn_kernel() {
    __shared__ float qs[Cc * QT];        // [k*128 + r]                (24 KB)
    __shared__ float ms[2][Cc * MT];     // [k*64 + perm(c)] ping-pong (24 KB)
    __shared__ float sqm[2][MT];

    int t    = threadIdx.x;
    int r0   = (t >> 3) * 4;      // 0,4,...,124
    int cs   = t & 7;             // column segment 0..7 (8 cols each)
    int cseg = cs * 8;
    int csegX = cseg ^ 32;        // sibling's column segment
    int hi   = (t & 4) ? 1 : 0;   // 0: own rows {0,1}; 1: own rows {2,3}
    int orow = hi * 2;
    int b    = blockIdx.y;
    int qBase = blockIdx.x * QT;
    int nodeBase = b * Nn;
    const float* xT = g_xnT + (size_t)b * Cc * Nn;

    // qs: straight coalesced copy (already k-major)
    for (int i = t; i < Cc * 32; i += 256) {
        int k = i >> 5, c4 = i & 31;
        *(float4*)&qs[k * QT + c4 * 4] =
            *(const float4*)&xT[k * Nn + qBase + c4 * 4];
    }
    // preload tile 0: col-chunk c4 -> float offset (c4&1)*32 + (c4>>1)*4
    for (int i = t; i < Cc * 16; i += 256) {
        int k = i >> 4, c4 = i & 15;
        int dp = ((c4 & 1) << 5) + ((c4 >> 1) << 2);
        *(float4*)&ms[0][k * MT + dp] =
            *(const float4*)&xT[k * Nn + c4 * 4];
    }
    if (t < MT) sqm[0][t] = g_sq[nodeBase + t];
    float sqqA = g_sq[nodeBase + qBase + r0 + orow];
    float sqqB = g_sq[nodeBase + qBase + r0 + orow + 1];

    // reg-resident top-9 lists for the 2 OWNED rows
    unsigned long long lstA[KK], lstB[KK];
#pragma unroll
    for (int s = 0; s < KK; s++) { lstA[s] = 0xFF800000FFFFFFFFULL; lstB[s] = 0xFF800000FFFFFFFFULL; }
    unsigned int thrA = 0xFF800000u, thrB = 0xFF800000u;

    __syncthreads();

    int p = 0;
    for (int mb = 0; mb < Nn; mb += MT) {
        if (mb + MT < Nn) {
            for (int i = t; i < Cc * 16; i += 256) {
                int k = i >> 4, c4 = i & 15;
                int dp = ((c4 & 1) << 5) + ((c4 >> 1) << 2);
                *(float4*)&ms[1 - p][k * MT + dp] =
                    *(const float4*)&xT[k * Nn + (mb + MT) + c4 * 4];
            }
            if (t < MT) sqm[1 - p][t] = g_sq[nodeBase + mb + MT + t];
        }

        const float* msp = ms[p];
        unsigned long long a[4][4];   // [row][col-pair]
#pragma unroll
        for (int r = 0; r < 4; r++)
#pragma unroll
            for (int j = 0; j < 4; j++) a[r][j] = 0ULL;

#pragma unroll 6
        for (int k = 0; k < Cc; k++) {
            float4 q4 = *(const float4*)&qs[k * QT + r0];
            unsigned long long q0 = pack_dup(q4.x);
            unsigned long long q1 = pack_dup(q4.y);
            unsigned long long q2 = pack_dup(q4.z);
            unsigned long long q3 = pack_dup(q4.w);
            const unsigned long long* mk =
                (const unsigned long long*)&msp[k * MT];
            unsigned long long m0 = mk[cs * 2],      m1 = mk[cs * 2 + 1];
            unsigned long long m2 = mk[16 + cs * 2], m3 = mk[16 + cs * 2 + 1];
            fma2(a[0][0], q0, m0); fma2(a[0][1], q0, m1);
            fma2(a[0][2], q0, m2); fma2(a[0][3], q0, m3);
            fma2(a[1][0], q1, m0); fma2(a[1][1], q1, m1);
            fma2(a[1][2], q1, m2); fma2(a[1][3], q1, m3);
            fma2(a[2][0], q2, m0); fma2(a[2][1], q2, m1);
            fma2(a[2][2], q2, m2); fma2(a[2][3], q2, m3);
            fma2(a[3][0], q3, m0); fma2(a[3][1], q3, m1);
            fma2(a[3][2], q3, m2); fma2(a[3][3], q3, m3);
        }

        // two selection phases: phase 0 handles row pair {0,2}; phase 1 {1,3}.
#pragma unroll
        for (int ph = 0; ph < 2; ph++) {
            float ownv[8], sendv[8];
#pragma unroll
            for (int j = 0; j < 4; j++) {
                float lo0, hi0, lo2, hi2;
                unpack2(a[0 + ph][j], lo0, hi0);   // row ph
                unpack2(a[2 + ph][j], lo2, hi2);   // row 2+ph
                ownv[2 * j]     = hi ? lo2 : lo0;
                ownv[2 * j + 1] = hi ? hi2 : hi0;
                sendv[2 * j]     = hi ? lo0 : lo2;
                sendv[2 * j + 1] = hi ? hi0 : hi2;
            }
            float recv[8];
#pragma unroll
            for (int j = 0; j < 8; j++)
                recv[j] = __shfl_xor_sync(0xffffffffu, sendv[j], 4);

            float sqq = ph ? sqqB : sqqA;
            unsigned int thr = ph ? thrB : thrA;
            unsigned long long* lst = ph ? lstB : lstA;

#pragma unroll
            for (int j = 0; j < 8; j++) {
                float d = (sqq + sqm[p][cseg + j]) - 2.f * ownv[j];
                unsigned int dm = fmono(d);
                if (dm <= thr) {
                    unsigned long long key =
                        ((unsigned long long)dm << 32) |
                        (unsigned int)(mb + cseg + j);
                    if (key < lst[KK - 1]) {
                        lst[KK - 1] = key;
#pragma unroll
                        for (int s = KK - 1; s > 0; --s) {
                            if (lst[s] < lst[s - 1]) {
                                unsigned long long tmp = lst[s];
                                lst[s] = lst[s - 1]; lst[s - 1] = tmp;
                            }
                        }
                        thr = (unsigned int)(lst[KK - 1] >> 32);
                    }
                }
                float d2 = (sqq + sqm[p][csegX + j]) - 2.f * recv[j];
                unsigned int dm2 = fmono(d2);
                if (dm2 <= thr) {
                    unsigned long long key =
                        ((unsigned long long)dm2 << 32) |
                        (unsigned int)(mb + csegX + j);
                    if (key < lst[KK - 1]) {
                        lst[KK - 1] = key;
#pragma unroll
                        for (int s = KK - 1; s > 0; --s) {
                            if (lst[s] < lst[s - 1]) {
                                unsigned long long tmp = lst[s];
                                lst[s] = lst[s - 1]; lst[s - 1] = tmp;
                            }
                        }
                        thr = (unsigned int)(lst[KK - 1] >> 32);
                    }
                }
            }
            if (ph) thrB = thr; else thrA = thr;
        }

        __syncthreads();
        p ^= 1;
    }

    // butterfly merge across the 4 threads (low-2-bit group) sharing owned rows
#pragma unroll
    for (int delta = 1; delta <= 2; delta <<= 1) {
        unsigned long long oA[KK], oB[KK];
#pragma unroll
        for (int s = 0; s < KK; s++) {
            oA[s] = __shfl_xor_sync(0xffffffffu, lstA[s], delta);
            oB[s] = __shfl_xor_sync(0xffffffffu, lstB[s], delta);
        }
#pragma unroll
        for (int s = 0; s < KK; s++) {
            if (oA[s] < lstA[KK - 1]) {
                lstA[KK - 1] = oA[s];
#pragma unroll
                for (int s2 = KK - 1; s2 > 0; --s2) {
                    if (lstA[s2] < lstA[s2 - 1]) {
                        unsigned long long tmp = lstA[s2];
                        lstA[s2] = lstA[s2 - 1]; lstA[s2 - 1] = tmp;
                    }
                }
            }
            if (oB[s] < lstB[KK - 1]) {
                lstB[KK - 1] = oB[s];
#pragma unroll
                for (int s2 = KK - 1; s2 > 0; --s2) {
                    if (lstB[s2] < lstB[s2 - 1]) {
                        unsigned long long tmp = lstB[s2];
                        lstB[s2] = lstB[s2 - 1]; lstB[s2 - 1] = tmp;
                    }
                }
            }
        }
    }

    if ((t & 3) == 0) {
        int nrow = nodeBase + qBase + r0 + orow;
#pragma unroll
        for (int s = 0; s < KK; s++) {
            g_nn[nrow * KK + s]       = (int)(unsigned int)(lstA[s] & 0xFFFFFFFFu);
            g_nn[(nrow + 1) * KK + s] = (int)(unsigned int)(lstB[s] & 0xFFFFFFFFu);
        }
    }
}

// ---------------- degree (int atomics: deterministic) ----------------
__global__ void deg_kernel() {
    int i = blockIdx.x * blockDim.x + threadIdx.x;
    if (i >= Ec) return;
    int cnt  = edge_count(i);
    int rown = i / KK;              // b*N + n
    int n    = rown & (Nn - 1);
    int m    = g_nn[i];
    int src  = m + cnt * Nn;
    int dst  = n + cnt * Nn;
    if (src < NBc && dst < NBc) atomicAdd(&g_deg[src], 1);
}

__global__ void dinv_kernel() {
    int i = blockIdx.x * blockDim.x + threadIdx.x;
    if (i >= NBc) return;
    int d = g_deg[i];
    g_dinv[i] = (d > 0) ? (1.0f / sqrtf((float)d)) : 0.0f;
}

// ---------------- Tx1: packed f32x2, one thread per (node, channel-pair) ----------------
// dst = q*N + n receives only from center rows (b', n) with b' in {q-1, q}
// whose edge index i has count(i)==q. Per-channel fmaf chain is element-wise
// identical to the scalar version (packed lanes are independent).
#define CP (Cc / 2)   // 24 channel pairs

__global__ void tx1_kernel() {
    int flat = blockIdx.x * blockDim.x + threadIdx.x;
    if (flat >= NBc * CP) return;
    int d  = flat / CP, cp = flat % CP;
    int ch = cp * 2;
    int q  = d >> 12, n = d & (Nn - 1);
    float dv = g_dinv[d];
    unsigned long long acc = 0ULL;
#pragma unroll
    for (int bb = 0; bb < 2; bb++) {
        int bp = q - 1 + bb;
        if (bp < 0 || bp >= Bc) continue;
        int ibase = (bp * Nn + n) * KK;
#pragma unroll
        for (int j = 0; j < KK; j++) {
            int i = ibase + j;
            if (edge_count(i) == q) {
                int src = g_nn[i] + q * Nn;   // always < NB since q <= 7
                unsigned long long w = pack_dup(-dv * g_dinv[src]);
                unsigned long long nv =
                    *(const unsigned long long*)&g_nodes[src * Cc + ch];
                fma2(acc, w, nv);
            }
        }
    }
    *(unsigned long long*)&g_tx1[d * Cc + ch] = acc;
}

// ---------------- epilogue: packed f32x2, one thread per output pair ----------------
__global__ void out_kernel(const float* __restrict__ W0, const float* __restrict__ W1,
                           const float* __restrict__ bias, float* __restrict__ out) {
    __shared__ float sW0[Cc * Cc], sW1[Cc * Cc], sb[Cc];
    int t = threadIdx.x;
    for (int i = t; i < Cc * Cc; i += blockDim.x) { sW0[i] = W0[i]; sW1[i] = W1[i]; }
    if (t < Cc) sb[t] = bias[t];
    __syncthreads();
    int flat = blockIdx.x * blockDim.x + t;
    if (flat >= NBc * CP) return;
    int d = flat / CP, cp = flat % CP;
    int co = cp * 2;
    const float* nrow = &g_nodes[d * Cc];
    const float* trow = &g_tx1[d * Cc];
    unsigned long long acc = *(const unsigned long long*)&sb[co];
#pragma unroll
    for (int k = 0; k < Cc; k++) {
        unsigned long long w1 = *(const unsigned long long*)&sW1[k * Cc + co];
        unsigned long long w0 = *(const unsigned long long*)&sW0[k * Cc + co];
        // per element: acc = fmaf(nrow[k], w0, fmaf(trow[k], w1, acc))
        fma2(acc, pack_dup(trow[k]), w1);
        fma2(acc, pack_dup(nrow[k]), w0);
    }
    *(unsigned long long*)&out[d * Cc + co] = acc;
}

// ---------------- launch ----------------
extern "C" void kernel_launch(void* const* d_in, const int* in_sizes, int n_in,
                              void* d_out, int out_size) {
    const float* x    = (const float*)d_in[0];
    const float* W0   = (const float*)d_in[1];
    const float* W1   = (const float*)d_in[2];
    const float* bias = (const float*)d_in[3];
    float* out = (float*)d_out;
    (void)in_sizes; (void)n_in; (void)out_size;

    prep_kernel<<<NBc / 256, 256>>>(x);
    dim3 gknn(Nn / QT, Bc);
    knn_kernel<<<gknn, 256>>>();
    deg_kernel<<<(Ec + 255) / 256, 256>>>();
    dinv_kernel<<<NBc / 256, 256>>>();
    tx1_kernel<<<(NBc * CP + 255) / 256, 256>>>();
    out_kernel<<<(NBc * CP + 255) / 256, 256>>>(W0, W1, bias, out);
}